// round 12
// baseline (speedup 1.0000x reference)
#include <cuda_runtime.h>
#include <cuda_bf16.h>
#include <math.h>
#include <stdint.h>

#define NN 50000
#define EE 800000

// ---------------- scratch (no cudaMalloc allowed) ----------------
__device__ __align__(16) float g_tmp[NN * 256];
__device__ __align__(16) float g_v[NN * 64];
__device__ __align__(16) float g_agg[NN * 64];
__device__ __align__(16) float g_rbf[EE * 12];
// bf16 hi/lo transposed weights: 10x[256x256] + 8x[64x256 / 256x64]
__device__ __align__(16) __nv_bfloat16 g_wh[10 * 65536 + 8 * 16384];
__device__ __align__(16) __nv_bfloat16 g_wl[10 * 65536 + 8 * 16384];

__device__ __forceinline__ uint32_t smem_u32(const void* p) {
    uint32_t a;
    asm("{ .reg .u64 t; cvta.to.shared.u64 t, %1; cvt.u32.u64 %0, t; }" : "=r"(a) : "l"(p));
    return a;
}

__device__ __forceinline__ void ldsm4(uint32_t& r0, uint32_t& r1, uint32_t& r2,
                                      uint32_t& r3, uint32_t addr) {
    asm volatile("ldmatrix.sync.aligned.m8n8.x4.shared.b16 {%0,%1,%2,%3}, [%4];"
                 : "=r"(r0), "=r"(r1), "=r"(r2), "=r"(r3) : "r"(addr));
}

__device__ __forceinline__ void mma_bf16(float* c, const uint32_t* a, const uint32_t* b) {
    asm volatile(
        "mma.sync.aligned.m16n8k16.row.col.f32.bf16.bf16.f32 "
        "{%0,%1,%2,%3}, {%4,%5,%6,%7}, {%8,%9}, {%0,%1,%2,%3};"
        : "+f"(c[0]), "+f"(c[1]), "+f"(c[2]), "+f"(c[3])
        : "r"(a[0]), "r"(a[1]), "r"(a[2]), "r"(a[3]), "r"(b[0]), "r"(b[1]));
}

__device__ __forceinline__ float gelu_f(float x) {
    float x3 = x * x * x;
    float t = tanhf(0.7978845608028654f * (x + 0.044715f * x3));
    return 0.5f * x * (1.0f + t);
}

__device__ __forceinline__ void split_bf16(float v, __nv_bfloat16& h, __nv_bfloat16& l) {
    h = __float2bfloat16(v);
    l = __float2bfloat16(v - __bfloat162float(h));
}

// Fast pair split: hi = truncated top-16-bits (1 PRMT per pair),
// lo = round-nearest bf16 of the fp32 remainder (1 cvt.bf16x2 per pair).
__device__ __forceinline__ void split_pair_fast(float a, float b,
                                                uint32_t& hpair, uint32_t& lpair) {
    uint32_t ua = __float_as_uint(a);
    uint32_t ub = __float_as_uint(b);
    hpair = __byte_perm(ua, ub, 0x7632);                 // {a_hi16, b_hi16}
    float ha = __uint_as_float(ua & 0xffff0000u);
    float hb = __uint_as_float(ub & 0xffff0000u);
    __nv_bfloat162 lo2 = __float22bfloat162_rn(make_float2(a - ha, b - hb));
    lpair = *reinterpret_cast<uint32_t*>(&lo2);
}

// ---------------------------------------------------------------------------
// Weight convert: W [nm][K x N] fp32 -> out [nm][N x K] bf16 hi/lo (transposed)
// (one-time; keeps the precise RN split)
// ---------------------------------------------------------------------------
__global__ void conv_w_kernel(const float* __restrict__ W,
                              __nv_bfloat16* __restrict__ oh,
                              __nv_bfloat16* __restrict__ ol,
                              int K, int Ncols, int total) {
    int idx = blockIdx.x * blockDim.x + threadIdx.x;
    if (idx >= total) return;
    int kn = K * Ncols;
    int m = idx / kn;
    int r = idx - m * kn;
    int n = r / K;
    int k = r - n * K;
    float w = W[(size_t)m * kn + (size_t)k * Ncols + n];
    split_bf16(w, oh[idx], ol[idx]);
}

// ---------------------------------------------------------------------------
// HMMA GEMM (R3-proven structure): CTA tile 128x64, BK=32, 256 threads.
// 3-product split: Ah*Bh + Ah*Bl + Al*Bh, fp32 accumulate.
// A staging uses the fast PRMT/trunc split.
// ---------------------------------------------------------------------------
template <bool BIAS, bool GELU, bool RESID>
__global__ void __launch_bounds__(256) mma_gemm(
    const float* __restrict__ A,
    const __nv_bfloat16* __restrict__ Bh_g,
    const __nv_bfloat16* __restrict__ Bl_g,
    const float* __restrict__ bias,
    float* __restrict__ C,
    int rows, int K, int ncols)
{
    constexpr int BM = 128, BN = 64, BK = 32, LD = 40;
    __shared__ __nv_bfloat16 sAh[BM * LD];
    __shared__ __nv_bfloat16 sAl[BM * LD];
    __shared__ __nv_bfloat16 sBh[BN * LD];
    __shared__ __nv_bfloat16 sBl[BN * LD];

    int tid = threadIdx.x;
    int lane = tid & 31;
    int wid = tid >> 5;
    int wm = wid & 3;
    int wn = wid >> 2;
    int r0 = blockIdx.y * BM;
    int c0 = blockIdx.x * BN;

    float acc[2][4][4];
#pragma unroll
    for (int i = 0; i < 2; i++)
#pragma unroll
        for (int j = 0; j < 4; j++)
#pragma unroll
            for (int k = 0; k < 4; k++) acc[i][j][k] = 0.f;

    uint32_t aH = smem_u32(sAh), aL = smem_u32(sAl);
    uint32_t bH = smem_u32(sBh), bL = smem_u32(sBl);

    int a_r = lane & 15;
    int a_c = (lane >> 4) * 8;
    int b_n = ((lane >> 4) * 8) + (lane & 7);
    int b_k = ((lane >> 3) & 1) * 8;

    int nkc = K / BK;
    for (int kc = 0; kc < nkc; kc++) {
        int k0 = kc * BK;
        {
            int c4 = tid & 7;
            int rr = tid >> 3;
#pragma unroll
            for (int q = 0; q < 4; q++) {
                int row = rr + q * 32;
                int gr = r0 + row;
                float4 a = make_float4(0.f, 0.f, 0.f, 0.f);
                if (gr < rows)
                    a = *reinterpret_cast<const float4*>(A + (size_t)gr * K + k0 + c4 * 4);
                uint2 uh, ul;
                split_pair_fast(a.x, a.y, uh.x, ul.x);
                split_pair_fast(a.z, a.w, uh.y, ul.y);
                *reinterpret_cast<uint2*>(sAh + row * LD + c4 * 4) = uh;
                *reinterpret_cast<uint2*>(sAl + row * LD + c4 * 4) = ul;
            }
        }
        {
            int rowb = tid >> 2;
            int c8 = tid & 3;
            size_t g = (size_t)(c0 + rowb) * K + k0 + c8 * 8;
            *reinterpret_cast<uint4*>(sBh + rowb * LD + c8 * 8) =
                *reinterpret_cast<const uint4*>(Bh_g + g);
            *reinterpret_cast<uint4*>(sBl + rowb * LD + c8 * 8) =
                *reinterpret_cast<const uint4*>(Bl_g + g);
        }
        __syncthreads();

#pragma unroll
        for (int kk = 0; kk < 2; kk++) {
            uint32_t ah[2][4], al[2][4], bh[2][4], bl[2][4];
#pragma unroll
            for (int im = 0; im < 2; im++) {
                uint32_t off = (uint32_t)(((wm * 32 + im * 16 + a_r) * LD + kk * 16 + a_c) * 2);
                ldsm4(ah[im][0], ah[im][1], ah[im][2], ah[im][3], aH + off);
                ldsm4(al[im][0], al[im][1], al[im][2], al[im][3], aL + off);
            }
#pragma unroll
            for (int jp = 0; jp < 2; jp++) {
                uint32_t off = (uint32_t)(((wn * 32 + jp * 16 + b_n) * LD + kk * 16 + b_k) * 2);
                ldsm4(bh[jp][0], bh[jp][1], bh[jp][2], bh[jp][3], bH + off);
                ldsm4(bl[jp][0], bl[jp][1], bl[jp][2], bl[jp][3], bL + off);
            }
#pragma unroll
            for (int im = 0; im < 2; im++)
#pragma unroll
                for (int jn = 0; jn < 4; jn++) {
                    const uint32_t* pbh = &bh[jn >> 1][(jn & 1) * 2];
                    const uint32_t* pbl = &bl[jn >> 1][(jn & 1) * 2];
                    mma_bf16(acc[im][jn], ah[im], pbh);
                    mma_bf16(acc[im][jn], ah[im], pbl);
                    mma_bf16(acc[im][jn], al[im], pbh);
                }
        }
        __syncthreads();
    }

#pragma unroll
    for (int im = 0; im < 2; im++) {
        int rowa = r0 + wm * 32 + im * 16 + (lane >> 2);
        int rowb2 = rowa + 8;
#pragma unroll
        for (int jn = 0; jn < 4; jn++) {
            int col = c0 + wn * 32 + jn * 8 + (lane & 3) * 2;
            float2 bv = make_float2(0.f, 0.f);
            if (BIAS) bv = *reinterpret_cast<const float2*>(bias + col);
#pragma unroll
            for (int h = 0; h < 2; h++) {
                int row = h ? rowb2 : rowa;
                if (row >= rows) continue;
                float vx = acc[im][jn][h * 2 + 0];
                float vy = acc[im][jn][h * 2 + 1];
                if (BIAS) { vx += bv.x; vy += bv.y; }
                if (GELU) { vx = gelu_f(vx); vy = gelu_f(vy); }
                float* p = C + (size_t)row * ncols + col;
                if (RESID) {
                    float2 old = *reinterpret_cast<const float2*>(p);
                    vx += old.x; vy += old.y;
                }
                *reinterpret_cast<float2*>(p) = make_float2(vx, vy);
            }
        }
    }
}

// ---------------------------------------------------------------------------
// Embedding init
// ---------------------------------------------------------------------------
__global__ void embed_kernel(const int* __restrict__ z,
                             const float* __restrict__ table,
                             const float* __restrict__ W,
                             const float* __restrict__ b,
                             float* __restrict__ x, int N) {
    int n = blockIdx.x;
    if (n >= N) return;
    int d = threadIdx.x;
    int t = z[n];
    float acc = b[d];
#pragma unroll
    for (int h = 0; h < 5; h++) acc += table[t * 5 + h] * W[h * 256 + d];
    x[(size_t)n * 256 + d] = acc;
}

// ---------------------------------------------------------------------------
// Bessel RBF with polynomial envelope (p=5): sincos + Chebyshev recurrence
// ---------------------------------------------------------------------------
__global__ void rbf_kernel(const int* __restrict__ ei,
                           const float* __restrict__ pos,
                           const float* __restrict__ freqs,
                           int E) {
    int e = blockIdx.x * blockDim.x + threadIdx.x;
    if (e >= E) return;
    int i = ei[e];
    int j = ei[E + e];
    float dx = pos[i * 3 + 0] - pos[j * 3 + 0];
    float dy = pos[i * 3 + 1] - pos[j * 3 + 1];
    float dz = pos[i * 3 + 2] - pos[j * 3 + 2];
    float dist = sqrtf(dx * dx + dy * dy + dz * dz + 1e-12f);
    float x = dist * 0.2f;
    float x2 = x * x;
    float x4 = x2 * x2;
    float env = 1.0f / x + (-21.0f) * x4 + 35.0f * x4 * x + (-15.0f) * x4 * x2;

    float f = freqs[0] * x;          // pi * x
    float s1, c1;
    sincosf(f, &s1, &c1);
    float twoc = 2.0f * c1;
    float sprev = 0.f, scur = s1;
    float* out = g_rbf + (size_t)e * 12;
#pragma unroll
    for (int r = 0; r < 12; r++) {
        out[r] = env * scur;
        float snext = twoc * scur - sprev;
        sprev = scur;
        scur = snext;
    }
}

// ---------------------------------------------------------------------------
// Edge messages + scatter: 16 threads/edge, rbf via 3x LDG.128,
// vector red.global.add.v4.f32
// ---------------------------------------------------------------------------
__global__ void edge_msg_kernel(const int* __restrict__ ei,
                                const float* __restrict__ Wrbf,  // [12,64]
                                int E) {
    __shared__ float sW[12 * 64];
    for (int t = threadIdx.x; t < 12 * 64; t += blockDim.x) sW[t] = Wrbf[t];
    __syncthreads();

    int gt = blockIdx.x * blockDim.x + threadIdx.x;
    int e = gt >> 4;
    if (e >= E) return;
    int sub = gt & 15;
    int m0 = sub * 4;

    int i = ei[e];
    int j = ei[E + e];

    const float4* rp = reinterpret_cast<const float4*>(g_rbf + (size_t)e * 12);
    float4 f0 = __ldg(rp);
    float4 f1 = __ldg(rp + 1);
    float4 f2 = __ldg(rp + 2);
    float r[12] = {f0.x, f0.y, f0.z, f0.w, f1.x, f1.y, f1.z, f1.w,
                   f2.x, f2.y, f2.z, f2.w};

    float gx = 0.f, gy = 0.f, gz = 0.f, gw = 0.f;
#pragma unroll
    for (int rr = 0; rr < 12; rr++) {
        const float* w = &sW[rr * 64 + m0];
        gx = fmaf(r[rr], w[0], gx);
        gy = fmaf(r[rr], w[1], gy);
        gz = fmaf(r[rr], w[2], gz);
        gw = fmaf(r[rr], w[3], gw);
    }
    const float4 vj = *reinterpret_cast<const float4*>(g_v + (size_t)j * 64 + m0);
    float vx = vj.x * gx, vy = vj.y * gy, vz = vj.z * gz, vw = vj.w * gw;
    float* dst = g_agg + (size_t)i * 64 + m0;
    asm volatile("red.global.add.v4.f32 [%0], {%1, %2, %3, %4};"
                 :: "l"(dst), "f"(vx), "f"(vy), "f"(vz), "f"(vw) : "memory");
}

// ---------------------------------------------------------------------------
// Launcher
// ---------------------------------------------------------------------------
extern "C" void kernel_launch(void* const* d_in, const int* in_sizes, int n_in,
                              void* d_out, int out_size) {
    const int* z = (const int*)d_in[0];
    const float* pos = (const float*)d_in[1];
    const int* ei = (const int*)d_in[4];
    const float* emb_table = (const float*)d_in[5];
    const float* emb_W = (const float*)d_in[6];
    const float* emb_b = (const float*)d_in[7];
    const float* freqs = (const float*)d_in[8];
    const float* fc0_W = (const float*)d_in[9];
    const float* fc0_b = (const float*)d_in[10];
    const float* conv_Wv = (const float*)d_in[11];
    const float* conv_Wrbf = (const float*)d_in[12];
    const float* conv_Wout = (const float*)d_in[13];
    const float* fc_W = (const float*)d_in[14];
    const float* fc_b = (const float*)d_in[15];

    int N = in_sizes[1] / 3;   // 50000
    int E = in_sizes[4] / 2;   // 800000

    float* x = (float*)d_out;

    float *tmp, *vbuf, *agg;
    __nv_bfloat16 *wh, *wl;
    cudaGetSymbolAddress((void**)&tmp, g_tmp);
    cudaGetSymbolAddress((void**)&vbuf, g_v);
    cudaGetSymbolAddress((void**)&agg, g_agg);
    cudaGetSymbolAddress((void**)&wh, g_wh);
    cudaGetSymbolAddress((void**)&wl, g_wl);

    // ---- weight conversion (hi/lo bf16, transposed) ----
    {
        int T = 2 * 65536;
        conv_w_kernel<<<(T + 255) / 256, 256>>>(fc0_W, wh, wl, 256, 256, T);
        T = 8 * 65536;
        conv_w_kernel<<<(T + 255) / 256, 256>>>(fc_W, wh + 2 * 65536, wl + 2 * 65536, 256, 256, T);
        T = 4 * 16384;
        conv_w_kernel<<<(T + 255) / 256, 256>>>(conv_Wv, wh + 655360, wl + 655360, 256, 64, T);
        conv_w_kernel<<<(T + 255) / 256, 256>>>(conv_Wout, wh + 655360 + 65536,
                                                wl + 655360 + 65536, 64, 256, T);
    }

    dim3 gridD(4, (N + 127) / 128);   // ncols=256
    dim3 gridM(1, (N + 127) / 128);   // ncols=64

    // 1. init embedding
    embed_kernel<<<N, 256>>>(z, emb_table, emb_W, emb_b, x, N);

    // 2. init FC block
    mma_gemm<true, true, false><<<gridD, 256>>>(x, wh, wl, fc0_b, tmp, N, 256, 256);
    mma_gemm<true, true, false><<<gridD, 256>>>(tmp, wh + 65536, wl + 65536,
                                                fc0_b + 256, x, N, 256, 256);

    // 3. radial basis
    rbf_kernel<<<(E + 255) / 256, 256>>>(ei, pos, freqs, E);

    // 4. interaction blocks
    for (int n = 0; n < 4; n++) {
        cudaMemsetAsync(agg, 0, (size_t)N * 64 * sizeof(float));

        // v = x @ Wv[n]
        mma_gemm<false, false, false><<<gridM, 256>>>(
            x, wh + 655360 + n * 16384, wl + 655360 + n * 16384, nullptr,
            vbuf, N, 256, 64);

        // gated messages + vector-red scatter
        edge_msg_kernel<<<(E * 16 + 255) / 256, 256>>>(
            ei, conv_Wrbf + (size_t)n * 12 * 64, E);

        // x = x + agg @ Wout[n]
        mma_gemm<false, false, true><<<gridD, 256>>>(
            agg, wh + 655360 + 65536 + n * 16384, wl + 655360 + 65536 + n * 16384,
            nullptr, x, N, 64, 256);

        // FC block
        const __nv_bfloat16* W0h = wh + (size_t)(2 + 2 * n) * 65536;
        const __nv_bfloat16* W0l = wl + (size_t)(2 + 2 * n) * 65536;
        const __nv_bfloat16* W1h = wh + (size_t)(3 + 2 * n) * 65536;
        const __nv_bfloat16* W1l = wl + (size_t)(3 + 2 * n) * 65536;
        const float* b0 = fc_b + (size_t)n * 2 * 256;
        const float* b1 = b0 + 256;
        mma_gemm<true, true, false><<<gridD, 256>>>(x, W0h, W0l, b0, tmp, N, 256, 256);
        mma_gemm<true, true, true><<<gridD, 256>>>(tmp, W1h, W1l, b1, x, N, 256, 256);
    }
}

// round 13
// speedup vs baseline: 1.2435x; 1.2435x over previous
#include <cuda_runtime.h>
#include <cuda_fp16.h>
#include <math.h>
#include <stdint.h>

#define NN 50000
#define EE 800000

// ---------------- scratch (no cudaMalloc allowed) ----------------
__device__ __align__(16) float g_tmp[NN * 256];
__device__ __align__(16) float g_v[NN * 64];
__device__ __align__(16) float g_agg[NN * 64];
__device__ __align__(16) float g_rbf[EE * 12];
// fp16 transposed weights: 10x[256x256] + 8x[64x256 / 256x64]
__device__ __align__(16) __half g_wf[10 * 65536 + 8 * 16384];

__device__ __forceinline__ uint32_t smem_u32(const void* p) {
    uint32_t a;
    asm("{ .reg .u64 t; cvta.to.shared.u64 t, %1; cvt.u32.u64 %0, t; }" : "=r"(a) : "l"(p));
    return a;
}

__device__ __forceinline__ void ldsm4(uint32_t& r0, uint32_t& r1, uint32_t& r2,
                                      uint32_t& r3, uint32_t addr) {
    asm volatile("ldmatrix.sync.aligned.m8n8.x4.shared.b16 {%0,%1,%2,%3}, [%4];"
                 : "=r"(r0), "=r"(r1), "=r"(r2), "=r"(r3) : "r"(addr));
}

__device__ __forceinline__ void mma_f16(float* c, const uint32_t* a, const uint32_t* b) {
    asm volatile(
        "mma.sync.aligned.m16n8k16.row.col.f32.f16.f16.f32 "
        "{%0,%1,%2,%3}, {%4,%5,%6,%7}, {%8,%9}, {%0,%1,%2,%3};"
        : "+f"(c[0]), "+f"(c[1]), "+f"(c[2]), "+f"(c[3])
        : "r"(a[0]), "r"(a[1]), "r"(a[2]), "r"(a[3]), "r"(b[0]), "r"(b[1]));
}

__device__ __forceinline__ float gelu_f(float x) {
    float x3 = x * x * x;
    float t = tanhf(0.7978845608028654f * (x + 0.044715f * x3));
    return 0.5f * x * (1.0f + t);
}

// ---------------------------------------------------------------------------
// Weight convert: W [nm][K x N] fp32 -> out [nm][N x K] fp16 (transposed, RN)
// ---------------------------------------------------------------------------
__global__ void conv_w_kernel(const float* __restrict__ W,
                              __half* __restrict__ of,
                              int K, int Ncols, int total) {
    int idx = blockIdx.x * blockDim.x + threadIdx.x;
    if (idx >= total) return;
    int kn = K * Ncols;
    int m = idx / kn;
    int r = idx - m * kn;
    int n = r / K;
    int k = r - n * K;
    of[idx] = __float2half_rn(W[(size_t)m * kn + (size_t)k * Ncols + n]);
}

// ---------------------------------------------------------------------------
// HMMA GEMM, single-product fp16 (fp32 accumulate).
// CTA tile 128x64, BK=32, 256 threads, 8 warps (4m x 2n), warp tile 32x32.
// ---------------------------------------------------------------------------
template <bool BIAS, bool GELU, bool RESID>
__global__ void __launch_bounds__(256) mma_gemm(
    const float* __restrict__ A,
    const __half* __restrict__ B_g,
    const float* __restrict__ bias,
    float* __restrict__ C,
    int rows, int K, int ncols)
{
    constexpr int BM = 128, BN = 64, BK = 32, LD = 40;
    __shared__ __half sA[BM * LD];
    __shared__ __half sB[BN * LD];

    int tid = threadIdx.x;
    int lane = tid & 31;
    int wid = tid >> 5;
    int wm = wid & 3;
    int wn = wid >> 2;
    int r0 = blockIdx.y * BM;
    int c0 = blockIdx.x * BN;

    float acc[2][4][4];
#pragma unroll
    for (int i = 0; i < 2; i++)
#pragma unroll
        for (int j = 0; j < 4; j++)
#pragma unroll
            for (int k = 0; k < 4; k++) acc[i][j][k] = 0.f;

    uint32_t aS = smem_u32(sA), bS = smem_u32(sB);

    int a_r = lane & 15;
    int a_c = (lane >> 4) * 8;
    int b_n = ((lane >> 4) * 8) + (lane & 7);
    int b_k = ((lane >> 3) & 1) * 8;

    int nkc = K / BK;
    for (int kc = 0; kc < nkc; kc++) {
        int k0 = kc * BK;
        // --- stage A [128 x 32] fp32 -> fp16 (RN) ---
        {
            int c4 = tid & 7;
            int rr = tid >> 3;
#pragma unroll
            for (int q = 0; q < 4; q++) {
                int row = rr + q * 32;
                int gr = r0 + row;
                float4 a = make_float4(0.f, 0.f, 0.f, 0.f);
                if (gr < rows)
                    a = *reinterpret_cast<const float4*>(A + (size_t)gr * K + k0 + c4 * 4);
                __half2 h01 = __floats2half2_rn(a.x, a.y);
                __half2 h23 = __floats2half2_rn(a.z, a.w);
                uint2 u = make_uint2(*reinterpret_cast<uint32_t*>(&h01),
                                     *reinterpret_cast<uint32_t*>(&h23));
                *reinterpret_cast<uint2*>(sA + row * LD + c4 * 4) = u;
            }
        }
        // --- stage B [64 x 32] fp16 copy ---
        {
            int rowb = tid >> 2;
            int c8 = tid & 3;
            size_t g = (size_t)(c0 + rowb) * K + k0 + c8 * 8;
            *reinterpret_cast<uint4*>(sB + rowb * LD + c8 * 8) =
                *reinterpret_cast<const uint4*>(B_g + g);
        }
        __syncthreads();

#pragma unroll
        for (int kk = 0; kk < 2; kk++) {
            uint32_t af[2][4], bf[2][4];
#pragma unroll
            for (int im = 0; im < 2; im++) {
                uint32_t off = (uint32_t)(((wm * 32 + im * 16 + a_r) * LD + kk * 16 + a_c) * 2);
                ldsm4(af[im][0], af[im][1], af[im][2], af[im][3], aS + off);
            }
#pragma unroll
            for (int jp = 0; jp < 2; jp++) {
                uint32_t off = (uint32_t)(((wn * 32 + jp * 16 + b_n) * LD + kk * 16 + b_k) * 2);
                ldsm4(bf[jp][0], bf[jp][1], bf[jp][2], bf[jp][3], bS + off);
            }
#pragma unroll
            for (int im = 0; im < 2; im++)
#pragma unroll
                for (int jn = 0; jn < 4; jn++)
                    mma_f16(acc[im][jn], af[im], &bf[jn >> 1][(jn & 1) * 2]);
        }
        __syncthreads();
    }

    // --- epilogue ---
#pragma unroll
    for (int im = 0; im < 2; im++) {
        int rowa = r0 + wm * 32 + im * 16 + (lane >> 2);
        int rowb2 = rowa + 8;
#pragma unroll
        for (int jn = 0; jn < 4; jn++) {
            int col = c0 + wn * 32 + jn * 8 + (lane & 3) * 2;
            float2 bv = make_float2(0.f, 0.f);
            if (BIAS) bv = *reinterpret_cast<const float2*>(bias + col);
#pragma unroll
            for (int h = 0; h < 2; h++) {
                int row = h ? rowb2 : rowa;
                if (row >= rows) continue;
                float vx = acc[im][jn][h * 2 + 0];
                float vy = acc[im][jn][h * 2 + 1];
                if (BIAS) { vx += bv.x; vy += bv.y; }
                if (GELU) { vx = gelu_f(vx); vy = gelu_f(vy); }
                float* p = C + (size_t)row * ncols + col;
                if (RESID) {
                    float2 old = *reinterpret_cast<const float2*>(p);
                    vx += old.x; vy += old.y;
                }
                *reinterpret_cast<float2*>(p) = make_float2(vx, vy);
            }
        }
    }
}

// ---------------------------------------------------------------------------
// Embedding init
// ---------------------------------------------------------------------------
__global__ void embed_kernel(const int* __restrict__ z,
                             const float* __restrict__ table,
                             const float* __restrict__ W,
                             const float* __restrict__ b,
                             float* __restrict__ x, int N) {
    int n = blockIdx.x;
    if (n >= N) return;
    int d = threadIdx.x;
    int t = z[n];
    float acc = b[d];
#pragma unroll
    for (int h = 0; h < 5; h++) acc += table[t * 5 + h] * W[h * 256 + d];
    x[(size_t)n * 256 + d] = acc;
}

// ---------------------------------------------------------------------------
// Bessel RBF with polynomial envelope (p=5): sincos + Chebyshev recurrence
// ---------------------------------------------------------------------------
__global__ void rbf_kernel(const int* __restrict__ ei,
                           const float* __restrict__ pos,
                           const float* __restrict__ freqs,
                           int E) {
    int e = blockIdx.x * blockDim.x + threadIdx.x;
    if (e >= E) return;
    int i = ei[e];
    int j = ei[E + e];
    float dx = pos[i * 3 + 0] - pos[j * 3 + 0];
    float dy = pos[i * 3 + 1] - pos[j * 3 + 1];
    float dz = pos[i * 3 + 2] - pos[j * 3 + 2];
    float dist = sqrtf(dx * dx + dy * dy + dz * dz + 1e-12f);
    float x = dist * 0.2f;
    float x2 = x * x;
    float x4 = x2 * x2;
    float env = 1.0f / x + (-21.0f) * x4 + 35.0f * x4 * x + (-15.0f) * x4 * x2;

    float f = freqs[0] * x;          // pi * x
    float s1, c1;
    sincosf(f, &s1, &c1);
    float twoc = 2.0f * c1;
    float sprev = 0.f, scur = s1;
    float* out = g_rbf + (size_t)e * 12;
#pragma unroll
    for (int r = 0; r < 12; r++) {
        out[r] = env * scur;
        float snext = twoc * scur - sprev;
        sprev = scur;
        scur = snext;
    }
}

// ---------------------------------------------------------------------------
// Edge messages + scatter: 16 threads/edge, rbf via 3x LDG.128,
// vector red.global.add.v4.f32
// ---------------------------------------------------------------------------
__global__ void edge_msg_kernel(const int* __restrict__ ei,
                                const float* __restrict__ Wrbf,  // [12,64]
                                int E) {
    __shared__ float sW[12 * 64];
    for (int t = threadIdx.x; t < 12 * 64; t += blockDim.x) sW[t] = Wrbf[t];
    __syncthreads();

    int gt = blockIdx.x * blockDim.x + threadIdx.x;
    int e = gt >> 4;
    if (e >= E) return;
    int sub = gt & 15;
    int m0 = sub * 4;

    int i = ei[e];
    int j = ei[E + e];

    const float4* rp = reinterpret_cast<const float4*>(g_rbf + (size_t)e * 12);
    float4 f0 = __ldg(rp);
    float4 f1 = __ldg(rp + 1);
    float4 f2 = __ldg(rp + 2);
    float r[12] = {f0.x, f0.y, f0.z, f0.w, f1.x, f1.y, f1.z, f1.w,
                   f2.x, f2.y, f2.z, f2.w};

    float gx = 0.f, gy = 0.f, gz = 0.f, gw = 0.f;
#pragma unroll
    for (int rr = 0; rr < 12; rr++) {
        const float* w = &sW[rr * 64 + m0];
        gx = fmaf(r[rr], w[0], gx);
        gy = fmaf(r[rr], w[1], gy);
        gz = fmaf(r[rr], w[2], gz);
        gw = fmaf(r[rr], w[3], gw);
    }
    const float4 vj = *reinterpret_cast<const float4*>(g_v + (size_t)j * 64 + m0);
    float vx = vj.x * gx, vy = vj.y * gy, vz = vj.z * gz, vw = vj.w * gw;
    float* dst = g_agg + (size_t)i * 64 + m0;
    asm volatile("red.global.add.v4.f32 [%0], {%1, %2, %3, %4};"
                 :: "l"(dst), "f"(vx), "f"(vy), "f"(vz), "f"(vw) : "memory");
}

// ---------------------------------------------------------------------------
// Launcher
// ---------------------------------------------------------------------------
extern "C" void kernel_launch(void* const* d_in, const int* in_sizes, int n_in,
                              void* d_out, int out_size) {
    const int* z = (const int*)d_in[0];
    const float* pos = (const float*)d_in[1];
    const int* ei = (const int*)d_in[4];
    const float* emb_table = (const float*)d_in[5];
    const float* emb_W = (const float*)d_in[6];
    const float* emb_b = (const float*)d_in[7];
    const float* freqs = (const float*)d_in[8];
    const float* fc0_W = (const float*)d_in[9];
    const float* fc0_b = (const float*)d_in[10];
    const float* conv_Wv = (const float*)d_in[11];
    const float* conv_Wrbf = (const float*)d_in[12];
    const float* conv_Wout = (const float*)d_in[13];
    const float* fc_W = (const float*)d_in[14];
    const float* fc_b = (const float*)d_in[15];

    int N = in_sizes[1] / 3;   // 50000
    int E = in_sizes[4] / 2;   // 800000

    float* x = (float*)d_out;

    float *tmp, *vbuf, *agg;
    __half* wf;
    cudaGetSymbolAddress((void**)&tmp, g_tmp);
    cudaGetSymbolAddress((void**)&vbuf, g_v);
    cudaGetSymbolAddress((void**)&agg, g_agg);
    cudaGetSymbolAddress((void**)&wf, g_wf);

    // ---- weight conversion (fp16, transposed) ----
    {
        int T = 2 * 65536;
        conv_w_kernel<<<(T + 255) / 256, 256>>>(fc0_W, wf, 256, 256, T);
        T = 8 * 65536;
        conv_w_kernel<<<(T + 255) / 256, 256>>>(fc_W, wf + 2 * 65536, 256, 256, T);
        T = 4 * 16384;
        conv_w_kernel<<<(T + 255) / 256, 256>>>(conv_Wv, wf + 655360, 256, 64, T);
        conv_w_kernel<<<(T + 255) / 256, 256>>>(conv_Wout, wf + 655360 + 65536, 64, 256, T);
    }

    dim3 gridD(4, (N + 127) / 128);   // ncols=256
    dim3 gridM(1, (N + 127) / 128);   // ncols=64

    // 1. init embedding
    embed_kernel<<<N, 256>>>(z, emb_table, emb_W, emb_b, x, N);

    // 2. init FC block
    mma_gemm<true, true, false><<<gridD, 256>>>(x, wf, fc0_b, tmp, N, 256, 256);
    mma_gemm<true, true, false><<<gridD, 256>>>(tmp, wf + 65536, fc0_b + 256, x, N, 256, 256);

    // 3. radial basis
    rbf_kernel<<<(E + 255) / 256, 256>>>(ei, pos, freqs, E);

    // 4. interaction blocks
    for (int n = 0; n < 4; n++) {
        cudaMemsetAsync(agg, 0, (size_t)N * 64 * sizeof(float));

        // v = x @ Wv[n]
        mma_gemm<false, false, false><<<gridM, 256>>>(
            x, wf + 655360 + n * 16384, nullptr, vbuf, N, 256, 64);

        // gated messages + vector-red scatter
        edge_msg_kernel<<<(E * 16 + 255) / 256, 256>>>(
            ei, conv_Wrbf + (size_t)n * 12 * 64, E);

        // x = x + agg @ Wout[n]
        mma_gemm<false, false, true><<<gridD, 256>>>(
            agg, wf + 655360 + 65536 + n * 16384, nullptr, x, N, 64, 256);

        // FC block
        const __half* W0 = wf + (size_t)(2 + 2 * n) * 65536;
        const __half* W1 = wf + (size_t)(3 + 2 * n) * 65536;
        const float* b0 = fc_b + (size_t)n * 2 * 256;
        const float* b1 = b0 + 256;
        mma_gemm<true, true, false><<<gridD, 256>>>(x, W0, b0, tmp, N, 256, 256);
        mma_gemm<true, true, true><<<gridD, 256>>>(tmp, W1, b1, x, N, 256, 256);
    }
}